// round 4
// baseline (speedup 1.0000x reference)
#include <cuda_runtime.h>
#include <cuda_fp16.h>

// SpatialTransformer: 3D trilinear warp, dense displacement field.
// vol: [B=2, D=160, H=160, W=160, C=2] f32, trf: [B,D,H,W,3] f32 -> out like vol.
//
// R4 scheme:
//  - E2[b][y][x][z] (z-INNERMOST): 2x2 (y,x)-corner block in fp16 (clipping
//    baked in), one uint4 (16B) per entry. The two z-planes a voxel needs are
//    CONTIGUOUS (same 128B line 7/8 of the time).
//  - Main kernel: 2 lanes per voxel (even lane -> z0 plane, odd -> z1 plane),
//    one 16B gather per lane; pair lands in ~1 line -> ~1.06 gather
//    wavefronts/voxel vs 2.0 before. Planes combined via shfl_xor.
//  - Prologue: smem-transpose (vol is x-contiguous, E2 is z-contiguous).
// Reference semantics preserved exactly:
//   l0c = clip(floor(loc),0,159); l1c = clip(l0c+1,0,159)
//   d1  = l1c - loc (floor weight, UNCLIPPED loc); d0 = 1 - d1

#define DIM  160
#define HALF 80
#define BD   320                 // B * D
#define SLAB (DIM * DIM)         // 25600
#define NVOX (BD * DIM * DIM)    // 8,192,000
#define TZ   16                  // z-tile in prologue
#define ZSTR 641                 // smem z-stride in words (2*160*2 + 1 pad)

// 131 MB scratch: corner-block volume, z-innermost (device global, no runtime alloc)
__device__ uint4 g_E2[NVOX];

static __device__ __forceinline__ unsigned pack_h2(float a, float b) {
    __half2 h = __floats2half2_rn(a, b);
    return *reinterpret_cast<unsigned*>(&h);
}
static __device__ __forceinline__ float2 h2f(unsigned u) {
    __half2 h = *reinterpret_cast<__half2*>(&u);
    return __half22float2(h);
}

// ---------------------------------------------------------------------------
// Prologue: build E2 with z-innermost layout via smem transpose.
// grid = (320 (b*DIM+y), 10 (z-tiles)), block = 256.
// ---------------------------------------------------------------------------
__global__ __launch_bounds__(256)
void build_E2_kernel(const float* __restrict__ vol)
{
    __shared__ float sm[TZ * ZSTR];   // 16*641*4 = 41 KB

    const int by = blockIdx.x;              // b*DIM + y
    const int b  = (by >= DIM) ? 1 : 0;
    const int y  = by - b * DIM;
    const int z0 = blockIdx.y * TZ;
    const int t  = threadIdx.x;
    const int yp = min(y + 1, DIM - 1);
    const float2* __restrict__ v2 = (const float2*)vol;

    // Load TZ z-planes x 2 y-rows x 160 x, coalesced in x.
    // j: x = j%160, rr = (j/160)&1, zz = j/320
    #pragma unroll
    for (int i = 0; i < (TZ * 2 * DIM) / 256; i++) {
        const int j  = i * 256 + t;
        const int x  = j % DIM;
        const int rr = (j / DIM) & 1;
        const int zz = j / (2 * DIM);
        const int yy = rr ? yp : y;
        const float2 v = v2[((b * DIM + z0 + zz) * DIM + yy) * DIM + x];
        sm[zz * ZSTR + rr * 320 + x * 2 + 0] = v.x;
        sm[zz * ZSTR + rr * 320 + x * 2 + 1] = v.y;
    }
    __syncthreads();

    // Emit entries; k: zz = k&15 (fast), x = k>>4 -> E2 writes z-contiguous.
    #pragma unroll
    for (int i = 0; i < (TZ * DIM) / 256; i++) {
        const int k  = i * 256 + t;
        const int zz = k & (TZ - 1);
        const int x  = k >> 4;
        const int xp = min(x + 1, DIM - 1);
        const float* s0 = &sm[zz * ZSTR];
        uint4 e;
        e.x = pack_h2(s0[x  * 2], s0[x  * 2 + 1]);        // (y  , x  )
        e.y = pack_h2(s0[xp * 2], s0[xp * 2 + 1]);        // (y  , x+1)
        e.z = pack_h2(s0[320 + x  * 2], s0[320 + x  * 2 + 1]); // (y+1, x  )
        e.w = pack_h2(s0[320 + xp * 2], s0[320 + xp * 2 + 1]); // (y+1, x+1)
        g_E2[(by * DIM + x) * DIM + (z0 + zz)] = e;
    }
}

// ---------------------------------------------------------------------------
// Main: 2 lanes per voxel (lane parity = z-plane), 2 voxels per lane-pair.
// grid = (320 (b*D+z), 80 (y)), block = 320 (160 pairs).
// ---------------------------------------------------------------------------
__global__ __launch_bounds__(2 * DIM)
void st_warp_kernel(const float* __restrict__ trf,
                    float* __restrict__ out)
{
    const int tid = threadIdx.x;
    const int s   = tid & 1;          // 0 -> z0 plane, 1 -> z1 plane
    const int x   = tid >> 1;         // 0..159
    const int y0  = blockIdx.y;       // 0..79
    const int zb  = blockIdx.x;       // 0..319 = b*D + z
    const int z   = (zb >= DIM) ? (zb - DIM) : zb;
    const int b   = (zb >= DIM) ? 1 : 0;
    const float maxl = (float)(DIM - 1);

    const int voxA = (zb * DIM + y0) * DIM + x;
    const int voxB = voxA + HALF * DIM;

    // trf loads (duplicated within a pair; warp-coalesced)
    const float tzA = trf[voxA * 3 + 0];
    const float tyA = trf[voxA * 3 + 1];
    const float txA = trf[voxA * 3 + 2];
    const float tzB = trf[voxB * 3 + 0];
    const float tyB = trf[voxB * 3 + 1];
    const float txB = trf[voxB * 3 + 2];

    // ---- voxel A index/weight math ----
    const float lzA = (float)z + tzA;
    const float lyA = (float)y0 + tyA;
    const float lxA = (float)x + txA;
    const float z0A = fminf(fmaxf(floorf(lzA), 0.0f), maxl);
    const float y0A = fminf(fmaxf(floorf(lyA), 0.0f), maxl);
    const float x0A = fminf(fmaxf(floorf(lxA), 0.0f), maxl);
    const float z1A = fminf(z0A + 1.0f, maxl);
    const float y1A = fminf(y0A + 1.0f, maxl);
    const float x1A = fminf(x0A + 1.0f, maxl);
    const float wzA0 = z1A - lzA, wzA1 = 1.0f - wzA0;
    const float wyA0 = y1A - lyA, wyA1 = 1.0f - wyA0;
    const float wxA0 = x1A - lxA, wxA1 = 1.0f - wxA0;
    const int   zsA  = s ? (int)z1A : (int)z0A;
    const float wzsA = s ? wzA1 : wzA0;
    const int   idxA = ((b * DIM + (int)y0A) * DIM + (int)x0A) * DIM + zsA;

    // ---- voxel B index/weight math ----
    const float lzB = (float)z + tzB;
    const float lyB = (float)(y0 + HALF) + tyB;
    const float lxB = (float)x + txB;
    const float z0B = fminf(fmaxf(floorf(lzB), 0.0f), maxl);
    const float y0B = fminf(fmaxf(floorf(lyB), 0.0f), maxl);
    const float x0B = fminf(fmaxf(floorf(lxB), 0.0f), maxl);
    const float z1B = fminf(z0B + 1.0f, maxl);
    const float y1B = fminf(y0B + 1.0f, maxl);
    const float x1B = fminf(x0B + 1.0f, maxl);
    const float wzB0 = z1B - lzB, wzB1 = 1.0f - wzB0;
    const float wyB0 = y1B - lyB, wyB1 = 1.0f - wyB0;
    const float wxB0 = x1B - lxB, wxB1 = 1.0f - wxB0;
    const int   zsB  = s ? (int)z1B : (int)z0B;
    const float wzsB = s ? wzB1 : wzB0;
    const int   idxB = ((b * DIM + (int)y0B) * DIM + (int)x0B) * DIM + zsB;

    // ---- 2 gathers in flight; lane-pair accesses land in ~1 line each ----
    const uint4 eA = g_E2[idxA];
    const uint4 eB = g_E2[idxB];

    // ---- voxel A: bilinear on this lane's z-plane, scaled by its z-weight ----
    float rA0, rA1;
    {
        const float w00 = wyA0 * wxA0, w01 = wyA0 * wxA1;
        const float w10 = wyA1 * wxA0, w11 = wyA1 * wxA1;
        const float2 c00 = h2f(eA.x), c01 = h2f(eA.y), c10 = h2f(eA.z), c11 = h2f(eA.w);
        float p0 = w00 * c00.x, p1 = w00 * c00.y;
        p0 = fmaf(w01, c01.x, p0);  p1 = fmaf(w01, c01.y, p1);
        p0 = fmaf(w10, c10.x, p0);  p1 = fmaf(w10, c10.y, p1);
        p0 = fmaf(w11, c11.x, p0);  p1 = fmaf(w11, c11.y, p1);
        rA0 = wzsA * p0;  rA1 = wzsA * p1;
    }
    // ---- voxel B ----
    float rB0, rB1;
    {
        const float w00 = wyB0 * wxB0, w01 = wyB0 * wxB1;
        const float w10 = wyB1 * wxB0, w11 = wyB1 * wxB1;
        const float2 c00 = h2f(eB.x), c01 = h2f(eB.y), c10 = h2f(eB.z), c11 = h2f(eB.w);
        float p0 = w00 * c00.x, p1 = w00 * c00.y;
        p0 = fmaf(w01, c01.x, p0);  p1 = fmaf(w01, c01.y, p1);
        p0 = fmaf(w10, c10.x, p0);  p1 = fmaf(w10, c10.y, p1);
        p0 = fmaf(w11, c11.x, p0);  p1 = fmaf(w11, c11.y, p1);
        rB0 = wzsB * p0;  rB1 = wzsB * p1;
    }

    // ---- combine the two z-planes across the lane pair ----
    rA0 += __shfl_xor_sync(0xffffffffu, rA0, 1);
    rA1 += __shfl_xor_sync(0xffffffffu, rA1, 1);
    rB0 += __shfl_xor_sync(0xffffffffu, rB0, 1);
    rB1 += __shfl_xor_sync(0xffffffffu, rB1, 1);

    // lane s stores channel s -> warp stores are 2 contiguous 128B runs
    out[voxA * 2 + s] = s ? rA1 : rA0;
    out[voxB * 2 + s] = s ? rB1 : rB0;
}

extern "C" void kernel_launch(void* const* d_in, const int* in_sizes, int n_in,
                              void* d_out, int out_size)
{
    const float* vol = (const float*)d_in[0];
    const float* trf = (const float*)d_in[1];
    float* out = (float*)d_out;

    dim3 pgrid(BD, DIM / TZ, 1);      // (b*DIM + y, z-tile)
    build_E2_kernel<<<pgrid, 256>>>(vol);

    dim3 mgrid(BD, HALF, 1);          // (b*D + z, y-half)
    st_warp_kernel<<<mgrid, 2 * DIM>>>(trf, out);
}

// round 5
// speedup vs baseline: 1.0967x; 1.0967x over previous
#include <cuda_runtime.h>
#include <cuda_fp16.h>

// SpatialTransformer: 3D trilinear warp, dense displacement field.
// vol: [B=2, D=160, H=160, W=160, C=2] f32, trf: [B,D,H,W,3] f32 -> out like vol.
//
// Scheme (R4/R5):
//  - E2[b][y][x][z] (z-INNERMOST): 2x2 (y,x)-corner block in fp16 (clip baked
//    in), one uint4 (16B) per entry; the two z-planes a voxel needs are
//    contiguous (same 128B line 7/8 of the time).
//  - Main: 2 lanes per voxel (even lane -> z0 plane, odd -> z1), one 16B
//    gather per lane; 4 voxels per lane for MLP; planes combined via shfl_xor.
//  - Prologue: float4-load / float2-smem transpose, conflict-padded.
// Reference semantics preserved exactly:
//   l0c = clip(floor(loc),0,159); l1c = clip(l0c+1,0,159)
//   d1  = l1c - loc (floor weight, UNCLIPPED loc); d0 = 1 - d1

#define DIM   160
#define BD    320                // B * D
#define NVOX  (BD * DIM * DIM)   // 8,192,000
#define TZ    16                 // z-tile in prologue
#define ZS2   323                // smem z-stride in float2 units (2*160 + 3 pad)

// 131 MB scratch: corner-block volume, z-innermost (device global, no runtime alloc)
__device__ uint4 g_E2[NVOX];

static __device__ __forceinline__ unsigned pack_h2(float a, float b) {
    __half2 h = __floats2half2_rn(a, b);
    return *reinterpret_cast<unsigned*>(&h);
}
static __device__ __forceinline__ unsigned pack_f2(float2 v) {
    return pack_h2(v.x, v.y);
}
static __device__ __forceinline__ float2 h2f(unsigned u) {
    __half2 h = *reinterpret_cast<__half2*>(&u);
    return __half22float2(h);
}

// ---------------------------------------------------------------------------
// Prologue: build E2 (z-innermost) via smem transpose.
// grid = (320 (b*DIM+y), 10 (z-tiles)), block = 256.
// ---------------------------------------------------------------------------
__global__ __launch_bounds__(256)
void build_E2_kernel(const float* __restrict__ vol)
{
    __shared__ float2 sm2[TZ * ZS2];   // 16*323*8 = 41.3 KB

    const int by = blockIdx.x;              // b*DIM + y
    const int b  = (by >= DIM) ? 1 : 0;
    const int y  = by - b * DIM;
    const int z0 = blockIdx.y * TZ;
    const int t  = threadIdx.x;
    const int yp = min(y + 1, DIM - 1);
    const float4* __restrict__ v4 = (const float4*)vol;

    // Load TZ z-planes x 2 y-rows x 160 x as float4 (2 voxels each), coalesced.
    // j: x4 = j%80, rr = (j/80)&1, zz = j/160   (10 iterations of 256)
    #pragma unroll
    for (int i = 0; i < (TZ * 2 * 80) / 256; i++) {
        const int j  = i * 256 + t;
        const int x4 = j % 80;
        const int rr = (j / 80) & 1;
        const int zz = j / 160;
        const int yy = rr ? yp : y;
        const float4 v = v4[((b * DIM + z0 + zz) * DIM + yy) * 80 + x4];
        float2* s = &sm2[zz * ZS2 + rr * DIM + x4 * 2];
        s[0] = make_float2(v.x, v.y);
        s[1] = make_float2(v.z, v.w);
    }
    __syncthreads();

    // Emit entries; k: zz = k&15, x = k>>4 -> E2 writes in 256B runs.
    #pragma unroll
    for (int i = 0; i < (TZ * DIM) / 256; i++) {
        const int k  = i * 256 + t;
        const int zz = k & (TZ - 1);
        const int x  = k >> 4;
        const int xp = min(x + 1, DIM - 1);
        const float2* s0 = &sm2[zz * ZS2];
        uint4 e;
        e.x = pack_f2(s0[x]);            // (y  , x  )
        e.y = pack_f2(s0[xp]);           // (y  , x+1)
        e.z = pack_f2(s0[DIM + x]);      // (y+1, x  )
        e.w = pack_f2(s0[DIM + xp]);     // (y+1, x+1)
        g_E2[(by * DIM + x) * DIM + (z0 + zz)] = e;
    }
}

// ---------------------------------------------------------------------------
// Main: 2 lanes per voxel (lane parity = z-plane), 4 voxels per lane.
// grid = (320 (b*D+z), 40), block = 320 (160 x-pairs); y = blockIdx.y*4 + q.
// ---------------------------------------------------------------------------
__global__ __launch_bounds__(2 * DIM)
void st_warp_kernel(const float* __restrict__ trf,
                    float* __restrict__ out)
{
    const int tid = threadIdx.x;
    const int s   = tid & 1;          // 0 -> z0 plane, 1 -> z1 plane
    const int x   = tid >> 1;         // 0..159
    const int yb  = blockIdx.y << 2;  // base y (0,4,...,156)
    const int zb  = blockIdx.x;       // 0..319 = b*D + z
    const int z   = (zb >= DIM) ? (zb - DIM) : zb;
    const int b   = (zb >= DIM) ? 1 : 0;
    const float maxl = (float)(DIM - 1);
    const float fz = (float)z;
    const float fx = (float)x;

    int   vox[4];
    float tz[4], ty[4], tx[4];
    #pragma unroll
    for (int q = 0; q < 4; q++) {
        vox[q] = (zb * DIM + (yb + q)) * DIM + x;
        tz[q] = trf[vox[q] * 3 + 0];
        ty[q] = trf[vox[q] * 3 + 1];
        tx[q] = trf[vox[q] * 3 + 2];
    }

    float wy0[4], wy1[4], wx0[4], wx1[4], wzs[4];
    int   idx[4];
    #pragma unroll
    for (int q = 0; q < 4; q++) {
        const float lz = fz + tz[q];
        const float ly = (float)(yb + q) + ty[q];
        const float lx = fx + tx[q];
        const float z0f = fminf(fmaxf(floorf(lz), 0.0f), maxl);
        const float y0f = fminf(fmaxf(floorf(ly), 0.0f), maxl);
        const float x0f = fminf(fmaxf(floorf(lx), 0.0f), maxl);
        const float z1f = fminf(z0f + 1.0f, maxl);
        const float y1f = fminf(y0f + 1.0f, maxl);
        const float x1f = fminf(x0f + 1.0f, maxl);
        wy0[q] = y1f - ly;  wy1[q] = 1.0f - wy0[q];
        wx0[q] = x1f - lx;  wx1[q] = 1.0f - wx0[q];
        const float wz0 = z1f - lz;
        wzs[q] = s ? (1.0f - wz0) : wz0;
        const int zs = s ? (int)z1f : (int)z0f;
        idx[q] = ((b * DIM + (int)y0f) * DIM + (int)x0f) * DIM + zs;
    }

    // 4 independent gathers in flight; lane-pair accesses share a line ~7/8.
    uint4 e[4];
    #pragma unroll
    for (int q = 0; q < 4; q++) e[q] = g_E2[idx[q]];

    #pragma unroll
    for (int q = 0; q < 4; q++) {
        const float w00 = wy0[q] * wx0[q], w01 = wy0[q] * wx1[q];
        const float w10 = wy1[q] * wx0[q], w11 = wy1[q] * wx1[q];
        const float2 c00 = h2f(e[q].x), c01 = h2f(e[q].y);
        const float2 c10 = h2f(e[q].z), c11 = h2f(e[q].w);
        float p0 = w00 * c00.x, p1 = w00 * c00.y;
        p0 = fmaf(w01, c01.x, p0);  p1 = fmaf(w01, c01.y, p1);
        p0 = fmaf(w10, c10.x, p0);  p1 = fmaf(w10, c10.y, p1);
        p0 = fmaf(w11, c11.x, p0);  p1 = fmaf(w11, c11.y, p1);
        float r0 = wzs[q] * p0;
        float r1 = wzs[q] * p1;
        // combine the two z-planes across the lane pair
        r0 += __shfl_xor_sync(0xffffffffu, r0, 1);
        r1 += __shfl_xor_sync(0xffffffffu, r1, 1);
        // lane s stores channel s -> warp stores are contiguous 128B runs
        out[vox[q] * 2 + s] = s ? r1 : r0;
    }
}

extern "C" void kernel_launch(void* const* d_in, const int* in_sizes, int n_in,
                              void* d_out, int out_size)
{
    const float* vol = (const float*)d_in[0];
    const float* trf = (const float*)d_in[1];
    float* out = (float*)d_out;

    dim3 pgrid(BD, DIM / TZ, 1);      // (b*DIM + y, z-tile)
    build_E2_kernel<<<pgrid, 256>>>(vol);

    dim3 mgrid(BD, DIM / 4, 1);       // (b*D + z, y/4)
    st_warp_kernel<<<mgrid, 2 * DIM>>>(trf, out);
}